// round 1
// baseline (speedup 1.0000x reference)
#include <cuda_runtime.h>
#include <cuda_bf16.h>
#include <cstdint>

// Problem constants (fixed shapes from reference)
#define BB   32      // batch
#define SS   512     // seq len
#define HH   768     // hidden
#define VV   8192    // vocab
#define WMAX 256     // words per sample

// ---------------------------------------------------------------------------
// Scratch: merged word embeddings [B*WMAX, H] fp32 (24 MB) as device global
// (no cudaMalloc allowed).
// ---------------------------------------------------------------------------
__device__ float g_merged[(size_t)BB * WMAX * HH];

// ---------------------------------------------------------------------------
// Kernel 1: segment mean. One block per (word w, batch b). segment_ids are
// sorted per row, so tokens for word w form a contiguous range found by
// binary search. Each token row is read exactly once across the grid.
// ---------------------------------------------------------------------------
__global__ void segmean_kernel(const float* __restrict__ enc,
                               const int*   __restrict__ ids) {
    const int w = blockIdx.x;
    const int b = blockIdx.y;
    const int* row = ids + b * SS;

    // lower_bound(w)
    int l = 0, r = SS;
    while (l < r) { int m = (l + r) >> 1; if (row[m] < w) l = m + 1; else r = m; }
    const int start = l;
    // lower_bound(w+1)
    r = SS;
    while (l < r) { int m = (l + r) >> 1; if (row[m] < w + 1) l = m + 1; else r = m; }
    const int end = l;

    const int cnt = end - start;
    const float inv = (cnt > 0) ? (1.0f / (float)cnt) : 0.0f;

    const float* base = enc + (size_t)b * SS * HH;
    float* out = g_merged + ((size_t)(b * WMAX + w)) * HH;

    for (int h = threadIdx.x; h < HH; h += blockDim.x) {
        float s = 0.0f;
        for (int t = start; t < end; ++t)
            s += base[(size_t)t * HH + h];
        out[h] = s * inv;
    }
}

// ---------------------------------------------------------------------------
// Kernel 2: SGEMM  C[M,N] = A[M,K] * B[K,N] + bias[N]
//   M = B*WMAX = 8192, K = H = 768, N = V = 8192. All divisible by tiles.
// Block tile 128x128, K-tile 16, 256 threads, 8x8 per-thread micro-tile.
// ---------------------------------------------------------------------------
#define BM 128
#define BN 128
#define BK 16
#define TM 8
#define TN 8

__global__ __launch_bounds__(256, 2)
void sgemm_kernel(const float* __restrict__ B_w,     // W [K, N]
                  const float* __restrict__ bias,    // [N]
                  float* __restrict__ C) {           // [M, N]
    const int M = BB * WMAX;   (void)M;
    const int N = VV;
    const int K = HH;

    __shared__ float As[BK][BM + 4];  // transposed A tile, padded
    __shared__ float Bs[BK][BN];

    const int tid = threadIdx.x;
    const int bm = blockIdx.y * BM;
    const int bn = blockIdx.x * BN;

    const int ty = tid >> 4;   // 0..15
    const int tx = tid & 15;   // 0..15

    const float* A = g_merged;

    float acc[TM][TN];
#pragma unroll
    for (int i = 0; i < TM; ++i)
#pragma unroll
        for (int j = 0; j < TN; ++j) acc[i][j] = 0.0f;

    for (int kt = 0; kt < K; kt += BK) {
        // Load A tile: 128 rows x 16 k = 512 float4 (4 float4 per row)
#pragma unroll
        for (int i = 0; i < 2; ++i) {
            int f   = tid + i * 256;          // 0..511
            int row = f >> 2;                 // 0..127
            int c4  = f & 3;                  // 0..3
            float4 v = *reinterpret_cast<const float4*>(
                &A[(size_t)(bm + row) * K + kt + c4 * 4]);
            As[c4 * 4 + 0][row] = v.x;
            As[c4 * 4 + 1][row] = v.y;
            As[c4 * 4 + 2][row] = v.z;
            As[c4 * 4 + 3][row] = v.w;
        }
        // Load B tile: 16 k-rows x 128 n = 512 float4 (32 float4 per row)
#pragma unroll
        for (int i = 0; i < 2; ++i) {
            int f   = tid + i * 256;
            int row = f >> 5;                 // 0..15
            int c4  = f & 31;                 // 0..31
            *reinterpret_cast<float4*>(&Bs[row][c4 * 4]) =
                *reinterpret_cast<const float4*>(
                    &B_w[(size_t)(kt + row) * N + bn + c4 * 4]);
        }
        __syncthreads();

#pragma unroll
        for (int k = 0; k < BK; ++k) {
            float ra[TM], rb[TN];
            float4 a0 = *reinterpret_cast<const float4*>(&As[k][ty * TM]);
            float4 a1 = *reinterpret_cast<const float4*>(&As[k][ty * TM + 4]);
            ra[0]=a0.x; ra[1]=a0.y; ra[2]=a0.z; ra[3]=a0.w;
            ra[4]=a1.x; ra[5]=a1.y; ra[6]=a1.z; ra[7]=a1.w;
            float4 b0 = *reinterpret_cast<const float4*>(&Bs[k][tx * TN]);
            float4 b1 = *reinterpret_cast<const float4*>(&Bs[k][tx * TN + 4]);
            rb[0]=b0.x; rb[1]=b0.y; rb[2]=b0.z; rb[3]=b0.w;
            rb[4]=b1.x; rb[5]=b1.y; rb[6]=b1.z; rb[7]=b1.w;
#pragma unroll
            for (int i = 0; i < TM; ++i)
#pragma unroll
                for (int j = 0; j < TN; ++j)
                    acc[i][j] = fmaf(ra[i], rb[j], acc[i][j]);
        }
        __syncthreads();
    }

    // Epilogue: bias add + vectorized store
#pragma unroll
    for (int i = 0; i < TM; ++i) {
        const int m = bm + ty * TM + i;
#pragma unroll
        for (int j = 0; j < TN; j += 4) {
            const int n = bn + tx * TN + j;
            float4 v;
            v.x = acc[i][j + 0] + bias[n + 0];
            v.y = acc[i][j + 1] + bias[n + 1];
            v.z = acc[i][j + 2] + bias[n + 2];
            v.w = acc[i][j + 3] + bias[n + 3];
            *reinterpret_cast<float4*>(&C[(size_t)m * N + n]) = v;
        }
    }
}

// ---------------------------------------------------------------------------
// Launch
// ---------------------------------------------------------------------------
extern "C" void kernel_launch(void* const* d_in, const int* in_sizes, int n_in,
                              void* d_out, int out_size) {
    const float* enc  = (const float*)d_in[0];   // [32,512,768] fp32
    const int*   ids  = (const int*)  d_in[1];   // [32,512] int32 (sorted per row)
    const float* W    = (const float*)d_in[2];   // [768,8192] fp32
    const float* bias = (const float*)d_in[3];   // [8192] fp32
    float* out = (float*)d_out;                  // [32,256,8192] fp32

    // Segment mean -> g_merged
    dim3 g1(WMAX, BB);
    segmean_kernel<<<g1, 256>>>(enc, ids);

    // GEMM + bias
    dim3 g2(VV / BN, (BB * WMAX) / BM);
    sgemm_kernel<<<g2, 256>>>(W, bias, out);
}

// round 3
// speedup vs baseline: 2.9131x; 2.9131x over previous
#include <cuda_runtime.h>
#include <cuda_bf16.h>
#include <cstdint>

#define BB   32
#define SS   512
#define HH   768
#define VV   8192
#define WMAX 256
#define MM   (BB * WMAX)       // 8192

// ---------------------------------------------------------------------------
// Device scratch (no cudaMalloc allowed).
// A (merged embeddings) hi/lo: [M, K] bf16 row-major.
// W hi/lo: [K, N] bf16 (original layout, no transpose).
// ---------------------------------------------------------------------------
__device__ __align__(16) __nv_bfloat16 g_a_hi[(size_t)MM * HH];
__device__ __align__(16) __nv_bfloat16 g_a_lo[(size_t)MM * HH];
__device__ __align__(16) __nv_bfloat16 g_w_hi[(size_t)HH * VV];
__device__ __align__(16) __nv_bfloat16 g_w_lo[(size_t)HH * VV];

// ---------------------------------------------------------------------------
// PTX helpers — all family-portable (sm_80+): cp.async, ldmatrix, mma.sync
// ---------------------------------------------------------------------------
__device__ __forceinline__ uint32_t smem_u32(const void* p) {
    uint32_t a;
    asm("{ .reg .u64 t; cvta.to.shared.u64 t, %1; cvt.u32.u64 %0, t; }" : "=r"(a) : "l"(p));
    return a;
}
__device__ __forceinline__ void cp16(uint32_t s, const void* g) {
    asm volatile("cp.async.cg.shared.global [%0], [%1], 16;" :: "r"(s), "l"(g));
}
__device__ __forceinline__ void ldsm4(uint32_t* r, uint32_t addr) {
    asm volatile("ldmatrix.sync.aligned.m8n8.x4.shared.b16 {%0,%1,%2,%3}, [%4];"
                 : "=r"(r[0]), "=r"(r[1]), "=r"(r[2]), "=r"(r[3]) : "r"(addr));
}
__device__ __forceinline__ void ldsm4t(uint32_t* r, uint32_t addr) {
    asm volatile("ldmatrix.sync.aligned.m8n8.x4.trans.shared.b16 {%0,%1,%2,%3}, [%4];"
                 : "=r"(r[0]), "=r"(r[1]), "=r"(r[2]), "=r"(r[3]) : "r"(addr));
}
__device__ __forceinline__ void mma_bf16(float* d, const uint32_t* a, const uint32_t* b) {
    asm volatile(
        "mma.sync.aligned.m16n8k16.row.col.f32.bf16.bf16.f32 "
        "{%0,%1,%2,%3}, {%4,%5,%6,%7}, {%8,%9}, {%0,%1,%2,%3};"
        : "+f"(d[0]), "+f"(d[1]), "+f"(d[2]), "+f"(d[3])
        : "r"(a[0]), "r"(a[1]), "r"(a[2]), "r"(a[3]), "r"(b[0]), "r"(b[1]));
}

// ---------------------------------------------------------------------------
// Kernel 1: segment mean -> bf16 hi/lo split, [M, K] row-major.
// ---------------------------------------------------------------------------
__global__ void segmean_split_kernel(const float* __restrict__ enc,
                                     const int*   __restrict__ ids) {
    const int w = blockIdx.x;
    const int b = blockIdx.y;
    const int* row = ids + b * SS;

    int l = 0, r = SS;
    while (l < r) { int m = (l + r) >> 1; if (row[m] < w) l = m + 1; else r = m; }
    const int start = l;
    r = SS;
    while (l < r) { int m = (l + r) >> 1; if (row[m] < w + 1) l = m + 1; else r = m; }
    const int end = l;

    const int cnt = end - start;
    const float inv = (cnt > 0) ? (1.0f / (float)cnt) : 0.0f;

    const float* base = enc + (size_t)b * SS * HH;
    const size_t orow = (size_t)(b * WMAX + w) * HH;

    for (int h = threadIdx.x; h < HH; h += blockDim.x) {
        float s = 0.0f;
        for (int t = start; t < end; ++t) s += base[(size_t)t * HH + h];
        float x = s * inv;
        __nv_bfloat16 hi = __float2bfloat16(x);
        float lo = x - __bfloat162float(hi);
        g_a_hi[orow + h] = hi;
        g_a_lo[orow + h] = __float2bfloat16(lo);
    }
}

// ---------------------------------------------------------------------------
// Kernel 2: elementwise split W [K, N] fp32 -> hi/lo bf16 (same layout).
// ---------------------------------------------------------------------------
__global__ void wsplit_kernel(const float* __restrict__ W) {
    size_t idx = (size_t)blockIdx.x * blockDim.x + threadIdx.x;
    const size_t total4 = (size_t)HH * VV / 4;
    if (idx >= total4) return;
    float4 v = reinterpret_cast<const float4*>(W)[idx];
    __nv_bfloat16 h0 = __float2bfloat16(v.x);
    __nv_bfloat16 h1 = __float2bfloat16(v.y);
    __nv_bfloat16 h2 = __float2bfloat16(v.z);
    __nv_bfloat16 h3 = __float2bfloat16(v.w);
    __nv_bfloat16 l0 = __float2bfloat16(v.x - __bfloat162float(h0));
    __nv_bfloat16 l1 = __float2bfloat16(v.y - __bfloat162float(h1));
    __nv_bfloat16 l2 = __float2bfloat16(v.z - __bfloat162float(h2));
    __nv_bfloat16 l3 = __float2bfloat16(v.w - __bfloat162float(h3));
    __nv_bfloat162* ph = reinterpret_cast<__nv_bfloat162*>(g_w_hi) + idx * 2;
    __nv_bfloat162* pl = reinterpret_cast<__nv_bfloat162*>(g_w_lo) + idx * 2;
    ph[0] = __nv_bfloat162(h0, h1); ph[1] = __nv_bfloat162(h2, h3);
    pl[0] = __nv_bfloat162(l0, l1); pl[1] = __nv_bfloat162(l2, l3);
}

// ---------------------------------------------------------------------------
// Kernel 3: HMMA GEMM.  C = A*W + bias, 3-term bf16 split, fp32 accum.
// CTA tile 128x256, BK=32, 4-stage cp.async pipeline, 8 warps (2x4), 64x64/warp.
// ---------------------------------------------------------------------------
#define BM 128
#define BN 256
#define BK 32
#define KTILES   (HH / BK)     // 24
#define STAGES   4
#define STAGE_B  49152         // 48 KB per stage
#define OFF_AH   0             // [128][32] bf16 = 8 KB   (64B rows)
#define OFF_AL   8192
#define OFF_BH   16384         // [32][256] bf16 = 16 KB  (512B rows)
#define OFF_BL   32768
#define SMEM_TOTAL (STAGES * STAGE_B)   // 196608

// swizzles (16B units XOR row bits), used identically by writer and reader
__device__ __forceinline__ uint32_t swA(uint32_t off) { return off ^ ((off >> 3) & 0x30); }
__device__ __forceinline__ uint32_t swB(uint32_t off) { return off ^ ((off >> 5) & 0x70); }

__global__ __launch_bounds__(256, 1)
void mma_gemm_kernel(const float* __restrict__ bias, float* __restrict__ C) {
    extern __shared__ char smem[];
    const uint32_t sb = smem_u32(smem);
    const int tid  = threadIdx.x;
    const int lane = tid & 31;
    const int wid  = tid >> 5;
    const int bm = blockIdx.y * BM;
    const int bn = blockIdx.x * BN;
    const int wm = (wid >> 2) * 64;   // warp M offset: 0 / 64
    const int wn = (wid & 3) * 64;    // warp N offset: 0..192

    float acc[4][8][4];
#pragma unroll
    for (int i = 0; i < 4; ++i)
#pragma unroll
        for (int j = 0; j < 8; ++j)
#pragma unroll
            for (int q = 0; q < 4; ++q) acc[i][j][q] = 0.0f;

    // ---- async stage loader ----
    auto load_stage = [&](int slot, int kt) {
        const uint32_t st = sb + slot * STAGE_B;
        const size_t ka = (size_t)kt * BK;
        // A hi/lo: 128 rows x 64B = 512 x 16B units each
#pragma unroll
        for (int it = 0; it < 2; ++it) {
            int p = tid + it * 256;
            int m = p >> 2, u = p & 3;
            uint32_t sw = swA((uint32_t)m * 64 + u * 16);
            size_t g = (size_t)(bm + m) * HH + ka + u * 8;
            cp16(st + OFF_AH + sw, g_a_hi + g);
            cp16(st + OFF_AL + sw, g_a_lo + g);
        }
        // B hi/lo: 32 rows x 512B = 1024 x 16B units each
#pragma unroll
        for (int it = 0; it < 4; ++it) {
            int p = tid + it * 256;
            int k = p >> 5, u = p & 31;
            uint32_t sw = swB((uint32_t)k * 512 + u * 16);
            size_t g = (size_t)(ka + k) * VV + bn + u * 8;
            cp16(st + OFF_BH + sw, g_w_hi + g);
            cp16(st + OFF_BL + sw, g_w_lo + g);
        }
        asm volatile("cp.async.commit_group;");
    };

    // prologue: fill STAGES-1 stages
#pragma unroll
    for (int s = 0; s < STAGES - 1; ++s) load_stage(s, s);

    for (int kt = 0; kt < KTILES; ++kt) {
        asm volatile("cp.async.wait_group 2;");
        __syncthreads();
        const uint32_t st = sb + (kt & (STAGES - 1)) * STAGE_B;

#pragma unroll
        for (int h = 0; h < 2; ++h) {           // two k16 sub-steps per BK=32
            const int k16 = h * 16;
            uint32_t ah[4][4], al[4][4];
#pragma unroll
            for (int i = 0; i < 4; ++i) {
                uint32_t row = wm + i * 16 + (lane & 15);
                uint32_t u = (uint32_t)(k16 >> 3) + (lane >> 4);
                uint32_t sw = swA(row * 64 + u * 16);
                ldsm4(ah[i], st + OFF_AH + sw);
                ldsm4(al[i], st + OFF_AL + sw);
            }
#pragma unroll
            for (int j = 0; j < 4; ++j) {       // 4 x n16 per warp
                uint32_t bk = (uint32_t)k16 + (lane & 15);
                uint32_t u = (uint32_t)((wn + 16 * j) >> 3) + (lane >> 4);
                uint32_t sw = swB(bk * 512 + u * 16);
                uint32_t bh[4], bl[4];
                ldsm4t(bh, st + OFF_BH + sw);
                ldsm4t(bl, st + OFF_BL + sw);
#pragma unroll
                for (int i = 0; i < 4; ++i) {
                    mma_bf16(acc[i][2 * j],     ah[i], bh);
                    mma_bf16(acc[i][2 * j],     al[i], bh);
                    mma_bf16(acc[i][2 * j],     ah[i], bl);
                    mma_bf16(acc[i][2 * j + 1], ah[i], bh + 2);
                    mma_bf16(acc[i][2 * j + 1], al[i], bh + 2);
                    mma_bf16(acc[i][2 * j + 1], ah[i], bl + 2);
                }
            }
        }
        // keep group numbering uniform: one commit per iteration
        if (kt + STAGES - 1 < KTILES) load_stage((kt + STAGES - 1) & (STAGES - 1), kt + STAGES - 1);
        else asm volatile("cp.async.commit_group;");
    }

    // ---- epilogue: bias + store ----
    const int rbase = bm + wm + (lane >> 2);
    const int cbase = bn + wn + (lane & 3) * 2;
#pragma unroll
    for (int j = 0; j < 8; ++j) {
        const int c = cbase + j * 8;
        const float bx = __ldg(&bias[c]);
        const float by = __ldg(&bias[c + 1]);
#pragma unroll
        for (int i = 0; i < 4; ++i) {
            const int r = rbase + i * 16;
            float2 v0 = make_float2(acc[i][j][0] + bx, acc[i][j][1] + by);
            float2 v1 = make_float2(acc[i][j][2] + bx, acc[i][j][3] + by);
            *reinterpret_cast<float2*>(&C[(size_t)r * VV + c]) = v0;
            *reinterpret_cast<float2*>(&C[(size_t)(r + 8) * VV + c]) = v1;
        }
    }
}

// ---------------------------------------------------------------------------
// Launch
// ---------------------------------------------------------------------------
extern "C" void kernel_launch(void* const* d_in, const int* in_sizes, int n_in,
                              void* d_out, int out_size) {
    const float* enc  = (const float*)d_in[0];   // [32,512,768]
    const int*   ids  = (const int*)  d_in[1];   // [32,512]
    const float* W    = (const float*)d_in[2];   // [768,8192]
    const float* bias = (const float*)d_in[3];   // [8192]
    float* out = (float*)d_out;                  // [32,256,8192]

    segmean_split_kernel<<<dim3(WMAX, BB), 256>>>(enc, ids);

    const size_t total4 = (size_t)HH * VV / 4;
    wsplit_kernel<<<(unsigned)((total4 + 255) / 256), 256>>>(W);

    cudaFuncSetAttribute(mma_gemm_kernel,
                         cudaFuncAttributeMaxDynamicSharedMemorySize, SMEM_TOTAL);
    mma_gemm_kernel<<<dim3(VV / BN, MM / BM), 256, SMEM_TOTAL>>>(bias, out);
}

// round 4
// speedup vs baseline: 4.3119x; 1.4801x over previous
#include <cuda_runtime.h>
#include <cuda_fp16.h>
#include <cstdint>

#define BB   32
#define SS   512
#define HH   768
#define VV   8192
#define WMAX 256
#define MM   (BB * WMAX)       // 8192

// ---------------------------------------------------------------------------
// Device scratch (no cudaMalloc allowed).
// A (merged embeddings) hi/lo: [M, K] fp16 row-major.  W: [K, N] fp16 single.
// ---------------------------------------------------------------------------
__device__ __align__(16) __half g_a_hi[(size_t)MM * HH];
__device__ __align__(16) __half g_a_lo[(size_t)MM * HH];
__device__ __align__(16) __half g_w[(size_t)HH * VV];

// ---------------------------------------------------------------------------
// PTX helpers — family-portable (sm_80+): cp.async, ldmatrix, mma.sync
// ---------------------------------------------------------------------------
__device__ __forceinline__ uint32_t smem_u32(const void* p) {
    uint32_t a;
    asm("{ .reg .u64 t; cvta.to.shared.u64 t, %1; cvt.u32.u64 %0, t; }" : "=r"(a) : "l"(p));
    return a;
}
__device__ __forceinline__ void cp16(uint32_t s, const void* g) {
    asm volatile("cp.async.cg.shared.global [%0], [%1], 16;" :: "r"(s), "l"(g));
}
__device__ __forceinline__ void ldsm4(uint32_t* r, uint32_t addr) {
    asm volatile("ldmatrix.sync.aligned.m8n8.x4.shared.b16 {%0,%1,%2,%3}, [%4];"
                 : "=r"(r[0]), "=r"(r[1]), "=r"(r[2]), "=r"(r[3]) : "r"(addr));
}
__device__ __forceinline__ void ldsm4t(uint32_t* r, uint32_t addr) {
    asm volatile("ldmatrix.sync.aligned.m8n8.x4.trans.shared.b16 {%0,%1,%2,%3}, [%4];"
                 : "=r"(r[0]), "=r"(r[1]), "=r"(r[2]), "=r"(r[3]) : "r"(addr));
}
__device__ __forceinline__ void mma_f16(float* d, const uint32_t* a, const uint32_t* b) {
    asm volatile(
        "mma.sync.aligned.m16n8k16.row.col.f32.f16.f16.f32 "
        "{%0,%1,%2,%3}, {%4,%5,%6,%7}, {%8,%9}, {%0,%1,%2,%3};"
        : "+f"(d[0]), "+f"(d[1]), "+f"(d[2]), "+f"(d[3])
        : "r"(a[0]), "r"(a[1]), "r"(a[2]), "r"(a[3]), "r"(b[0]), "r"(b[1]));
}

// ---------------------------------------------------------------------------
// Kernel 1: segment mean -> fp16 hi/lo split, [M, K] row-major.
// One block per (w, b); 192 threads, one float4 (4 h's) per thread.
// id row cached in smem; binary search runs in smem, not global.
// ---------------------------------------------------------------------------
__global__ __launch_bounds__(192)
void segmean_split_kernel(const float* __restrict__ enc,
                          const int*   __restrict__ ids) {
    __shared__ int srow[SS];
    const int w = blockIdx.x;
    const int b = blockIdx.y;
    const int tid = threadIdx.x;

    for (int i = tid; i < SS; i += 192) srow[i] = ids[b * SS + i];
    __syncthreads();

    int l = 0, r = SS;
    while (l < r) { int m = (l + r) >> 1; if (srow[m] < w) l = m + 1; else r = m; }
    const int start = l;
    r = SS;
    while (l < r) { int m = (l + r) >> 1; if (srow[m] < w + 1) l = m + 1; else r = m; }
    const int end = l;

    const int cnt = end - start;
    const float inv = (cnt > 0) ? (1.0f / (float)cnt) : 0.0f;

    const float* base = enc + (size_t)b * SS * HH + tid * 4;
    const size_t orow = (size_t)(b * WMAX + w) * HH + tid * 4;

    float4 s0 = make_float4(0.f, 0.f, 0.f, 0.f);
    float4 s1 = make_float4(0.f, 0.f, 0.f, 0.f);
    int t = start;
    for (; t + 1 < end; t += 2) {
        float4 v0 = *reinterpret_cast<const float4*>(base + (size_t)t * HH);
        float4 v1 = *reinterpret_cast<const float4*>(base + (size_t)(t + 1) * HH);
        s0.x += v0.x; s0.y += v0.y; s0.z += v0.z; s0.w += v0.w;
        s1.x += v1.x; s1.y += v1.y; s1.z += v1.z; s1.w += v1.w;
    }
    if (t < end) {
        float4 v0 = *reinterpret_cast<const float4*>(base + (size_t)t * HH);
        s0.x += v0.x; s0.y += v0.y; s0.z += v0.z; s0.w += v0.w;
    }
    float x0 = (s0.x + s1.x) * inv, x1 = (s0.y + s1.y) * inv;
    float x2 = (s0.z + s1.z) * inv, x3 = (s0.w + s1.w) * inv;

    __half h0 = __float2half_rn(x0), h1 = __float2half_rn(x1);
    __half h2 = __float2half_rn(x2), h3 = __float2half_rn(x3);
    __half l0 = __float2half_rn(x0 - __half2float(h0));
    __half l1 = __float2half_rn(x1 - __half2float(h1));
    __half l2 = __float2half_rn(x2 - __half2float(h2));
    __half l3 = __float2half_rn(x3 - __half2float(h3));

    __half2* ph = reinterpret_cast<__half2*>(g_a_hi + orow);
    __half2* pl = reinterpret_cast<__half2*>(g_a_lo + orow);
    ph[0] = __halves2half2(h0, h1); ph[1] = __halves2half2(h2, h3);
    pl[0] = __halves2half2(l0, l1); pl[1] = __halves2half2(l2, l3);
}

// ---------------------------------------------------------------------------
// Kernel 2: W [K, N] fp32 -> fp16 (same layout).
// ---------------------------------------------------------------------------
__global__ void wconv_kernel(const float* __restrict__ W) {
    size_t idx = (size_t)blockIdx.x * blockDim.x + threadIdx.x;
    const size_t total4 = (size_t)HH * VV / 4;
    if (idx >= total4) return;
    float4 v = reinterpret_cast<const float4*>(W)[idx];
    __half2* p = reinterpret_cast<__half2*>(g_w) + idx * 2;
    p[0] = __halves2half2(__float2half_rn(v.x), __float2half_rn(v.y));
    p[1] = __halves2half2(__float2half_rn(v.z), __float2half_rn(v.w));
}

// ---------------------------------------------------------------------------
// Kernel 3: HMMA GEMM.  C = (Ah + Al) * W + bias, fp32 accum.
// CTA 128x128, BK=32, 4-stage cp.async, 4 warps (2x2), 64x64 per warp.
// 2 CTAs / SM (96 KB smem each).
// ---------------------------------------------------------------------------
#define BM 128
#define BN 128
#define BK 32
#define KTILES   (HH / BK)     // 24
#define STAGES   4
#define OFF_AH   0             // [128][32] fp16 = 8 KB (64B rows)
#define OFF_AL   8192
#define OFF_B    16384         // [32][128] fp16 = 8 KB (256B rows)
#define STAGE_B  24576
#define SMEM_TOTAL (STAGES * STAGE_B)   // 98304

__device__ __forceinline__ uint32_t swA(uint32_t off) { return off ^ ((off >> 3) & 0x30); }
__device__ __forceinline__ uint32_t swB(uint32_t off) { return off ^ ((off >> 4) & 0x70); }

__global__ __launch_bounds__(128, 2)
void mma_gemm_kernel(const float* __restrict__ bias, float* __restrict__ C) {
    extern __shared__ char smem[];
    const uint32_t sb = smem_u32(smem);
    const int tid  = threadIdx.x;
    const int lane = tid & 31;
    const int wid  = tid >> 5;
    const int bm = blockIdx.y * BM;
    const int bn = blockIdx.x * BN;
    const int wm = (wid >> 1) * 64;
    const int wn = (wid & 1) * 64;

    float acc[4][8][4];
#pragma unroll
    for (int i = 0; i < 4; ++i)
#pragma unroll
        for (int j = 0; j < 8; ++j)
#pragma unroll
            for (int q = 0; q < 4; ++q) acc[i][j][q] = 0.0f;

    auto load_stage = [&](int slot, int kt) {
        const uint32_t st = sb + slot * STAGE_B;
        const size_t ka = (size_t)kt * BK;
        // A hi/lo: 128 rows x 4 x 16B units
#pragma unroll
        for (int it = 0; it < 4; ++it) {
            int p = tid + it * 128;
            int m = p >> 2, u = p & 3;
            uint32_t sw = swA((uint32_t)m * 64 + u * 16);
            size_t g = (size_t)(bm + m) * HH + ka + u * 8;
            cp16(st + OFF_AH + sw, g_a_hi + g);
            cp16(st + OFF_AL + sw, g_a_lo + g);
        }
        // B: 32 rows x 16 x 16B units
#pragma unroll
        for (int it = 0; it < 4; ++it) {
            int p = tid + it * 128;
            int k = p >> 4, u = p & 15;
            uint32_t sw = swB((uint32_t)k * 256 + u * 16);
            size_t g = (size_t)(ka + k) * VV + bn + u * 8;
            cp16(st + OFF_B + sw, g_w + g);
        }
        asm volatile("cp.async.commit_group;");
    };

#pragma unroll
    for (int s = 0; s < STAGES - 1; ++s) load_stage(s, s);

    for (int kt = 0; kt < KTILES; ++kt) {
        asm volatile("cp.async.wait_group 2;");
        __syncthreads();
        const uint32_t st = sb + (kt & (STAGES - 1)) * STAGE_B;

#pragma unroll
        for (int h = 0; h < 2; ++h) {
            const int k16 = h * 16;
            uint32_t ah[4][4], al[4][4];
#pragma unroll
            for (int i = 0; i < 4; ++i) {
                uint32_t row = wm + i * 16 + (lane & 15);
                uint32_t u = (uint32_t)(k16 >> 3) + (lane >> 4);
                uint32_t sw = swA(row * 64 + u * 16);
                ldsm4(ah[i], st + OFF_AH + sw);
                ldsm4(al[i], st + OFF_AL + sw);
            }
#pragma unroll
            for (int j = 0; j < 4; ++j) {
                uint32_t bk = (uint32_t)k16 + (lane & 15);
                uint32_t u = (uint32_t)((wn + 16 * j) >> 3) + (lane >> 4);
                uint32_t sw = swB(bk * 256 + u * 16);
                uint32_t bb[4];
                ldsm4t(bb, st + OFF_B + sw);
#pragma unroll
                for (int i = 0; i < 4; ++i) {
                    mma_f16(acc[i][2 * j],     ah[i], bb);
                    mma_f16(acc[i][2 * j],     al[i], bb);
                    mma_f16(acc[i][2 * j + 1], ah[i], bb + 2);
                    mma_f16(acc[i][2 * j + 1], al[i], bb + 2);
                }
            }
        }
        if (kt + STAGES - 1 < KTILES) load_stage((kt + STAGES - 1) & (STAGES - 1), kt + STAGES - 1);
        else asm volatile("cp.async.commit_group;");
    }

    // ---- epilogue: bias + store ----
    const int rbase = bm + wm + (lane >> 2);
    const int cbase = bn + wn + (lane & 3) * 2;
#pragma unroll
    for (int j = 0; j < 8; ++j) {
        const int c = cbase + j * 8;
        const float bx = __ldg(&bias[c]);
        const float by = __ldg(&bias[c + 1]);
#pragma unroll
        for (int i = 0; i < 4; ++i) {
            const int r = rbase + i * 16;
            float2 v0 = make_float2(acc[i][j][0] + bx, acc[i][j][1] + by);
            float2 v1 = make_float2(acc[i][j][2] + bx, acc[i][j][3] + by);
            *reinterpret_cast<float2*>(&C[(size_t)r * VV + c]) = v0;
            *reinterpret_cast<float2*>(&C[(size_t)(r + 8) * VV + c]) = v1;
        }
    }
}

// ---------------------------------------------------------------------------
// Launch
// ---------------------------------------------------------------------------
extern "C" void kernel_launch(void* const* d_in, const int* in_sizes, int n_in,
                              void* d_out, int out_size) {
    const float* enc  = (const float*)d_in[0];   // [32,512,768]
    const int*   ids  = (const int*)  d_in[1];   // [32,512]
    const float* W    = (const float*)d_in[2];   // [768,8192]
    const float* bias = (const float*)d_in[3];   // [8192]
    float* out = (float*)d_out;                  // [32,256,8192]

    segmean_split_kernel<<<dim3(WMAX, BB), 192>>>(enc, ids);

    const size_t total4 = (size_t)HH * VV / 4;
    wconv_kernel<<<(unsigned)((total4 + 255) / 256), 256>>>(W);

    cudaFuncSetAttribute(mma_gemm_kernel,
                         cudaFuncAttributeMaxDynamicSharedMemorySize, SMEM_TOTAL);
    mma_gemm_kernel<<<dim3(VV / BN, MM / BM), 128, SMEM_TOTAL>>>(bias, out);
}

// round 5
// speedup vs baseline: 7.2980x; 1.6925x over previous
#include <cuda_runtime.h>
#include <cuda_fp16.h>
#include <cstdint>

#define BB   32
#define SS   512
#define HH   768
#define VV   8192
#define WMAX 256
#define MM   (BB * WMAX)       // 8192

// ---------------------------------------------------------------------------
// Device scratch: A (merged) fp16 [M, K] row-major; W fp16 [K, N].
// ---------------------------------------------------------------------------
__device__ __align__(16) __half g_a[(size_t)MM * HH];
__device__ __align__(16) __half g_w[(size_t)HH * VV];

// ---------------------------------------------------------------------------
// PTX helpers — family-portable (sm_80+)
// ---------------------------------------------------------------------------
__device__ __forceinline__ uint32_t smem_u32(const void* p) {
    uint32_t a;
    asm("{ .reg .u64 t; cvta.to.shared.u64 t, %1; cvt.u32.u64 %0, t; }" : "=r"(a) : "l"(p));
    return a;
}
__device__ __forceinline__ void cp16(uint32_t s, const void* g) {
    asm volatile("cp.async.cg.shared.global [%0], [%1], 16;" :: "r"(s), "l"(g));
}
__device__ __forceinline__ void ldsm4(uint32_t* r, uint32_t addr) {
    asm volatile("ldmatrix.sync.aligned.m8n8.x4.shared.b16 {%0,%1,%2,%3}, [%4];"
                 : "=r"(r[0]), "=r"(r[1]), "=r"(r[2]), "=r"(r[3]) : "r"(addr));
}
__device__ __forceinline__ void ldsm4t(uint32_t* r, uint32_t addr) {
    asm volatile("ldmatrix.sync.aligned.m8n8.x4.trans.shared.b16 {%0,%1,%2,%3}, [%4];"
                 : "=r"(r[0]), "=r"(r[1]), "=r"(r[2]), "=r"(r[3]) : "r"(addr));
}
__device__ __forceinline__ void mma_f16(float* d, const uint32_t* a, const uint32_t* b) {
    asm volatile(
        "mma.sync.aligned.m16n8k16.row.col.f32.f16.f16.f32 "
        "{%0,%1,%2,%3}, {%4,%5,%6,%7}, {%8,%9}, {%0,%1,%2,%3};"
        : "+f"(d[0]), "+f"(d[1]), "+f"(d[2]), "+f"(d[3])
        : "r"(a[0]), "r"(a[1]), "r"(a[2]), "r"(a[3]), "r"(b[0]), "r"(b[1]));
}

// ---------------------------------------------------------------------------
// Kernel 1: segment mean -> fp16, [M, K] row-major. 8 words per block;
// ids row loaded to smem once per block, binary searches run in smem.
// ---------------------------------------------------------------------------
#define WPB 8
__global__ __launch_bounds__(192)
void segmean_kernel(const float* __restrict__ enc,
                    const int*   __restrict__ ids) {
    __shared__ int srow[SS];
    const int b = blockIdx.y;
    const int w0 = blockIdx.x * WPB;
    const int tid = threadIdx.x;

    for (int i = tid; i < SS; i += 192) srow[i] = ids[b * SS + i];
    __syncthreads();

    const float* base = enc + (size_t)b * SS * HH + tid * 4;

#pragma unroll
    for (int wl = 0; wl < WPB; ++wl) {
        const int w = w0 + wl;
        int l = 0, r = SS;
        while (l < r) { int m = (l + r) >> 1; if (srow[m] < w) l = m + 1; else r = m; }
        const int start = l;
        r = SS;
        while (l < r) { int m = (l + r) >> 1; if (srow[m] < w + 1) l = m + 1; else r = m; }
        const int end = l;

        const int cnt = end - start;
        const float inv = (cnt > 0) ? (1.0f / (float)cnt) : 0.0f;

        float4 s0 = make_float4(0.f, 0.f, 0.f, 0.f);
        float4 s1 = make_float4(0.f, 0.f, 0.f, 0.f);
        int t = start;
        for (; t + 1 < end; t += 2) {
            float4 v0 = *reinterpret_cast<const float4*>(base + (size_t)t * HH);
            float4 v1 = *reinterpret_cast<const float4*>(base + (size_t)(t + 1) * HH);
            s0.x += v0.x; s0.y += v0.y; s0.z += v0.z; s0.w += v0.w;
            s1.x += v1.x; s1.y += v1.y; s1.z += v1.z; s1.w += v1.w;
        }
        if (t < end) {
            float4 v0 = *reinterpret_cast<const float4*>(base + (size_t)t * HH);
            s0.x += v0.x; s0.y += v0.y; s0.z += v0.z; s0.w += v0.w;
        }
        const size_t orow = (size_t)(b * WMAX + w) * HH + tid * 4;
        __half2* p = reinterpret_cast<__half2*>(g_a + orow);
        p[0] = __halves2half2(__float2half_rn((s0.x + s1.x) * inv),
                              __float2half_rn((s0.y + s1.y) * inv));
        p[1] = __halves2half2(__float2half_rn((s0.z + s1.z) * inv),
                              __float2half_rn((s0.w + s1.w) * inv));
    }
}

// ---------------------------------------------------------------------------
// Kernel 2: W [K, N] fp32 -> fp16 (same layout).
// ---------------------------------------------------------------------------
__global__ void wconv_kernel(const float* __restrict__ W) {
    size_t idx = (size_t)blockIdx.x * blockDim.x + threadIdx.x;
    const size_t total4 = (size_t)HH * VV / 4;
    if (idx >= total4) return;
    float4 v = reinterpret_cast<const float4*>(W)[idx];
    __half2* p = reinterpret_cast<__half2*>(g_w) + idx * 2;
    p[0] = __halves2half2(__float2half_rn(v.x), __float2half_rn(v.y));
    p[1] = __halves2half2(__float2half_rn(v.z), __float2half_rn(v.w));
}

// ---------------------------------------------------------------------------
// Kernel 3: HMMA GEMM.  C = A * W + bias, single fp16 term, fp32 accum.
// CTA 128x128, BK=32, 4-stage cp.async, 8 warps (2x4), warp tile 64x32.
// 2 CTAs / SM (64 KB smem, <=128 regs/thread).
// ---------------------------------------------------------------------------
#define BM 128
#define BN 128
#define BK 32
#define KTILES   (HH / BK)     // 24
#define STAGES   4
#define OFF_A    0             // [128][32] fp16 = 8 KB (64B rows)
#define OFF_B    8192          // [32][128] fp16 = 8 KB (256B rows)
#define STAGE_B  16384
#define SMEM_TOTAL (STAGES * STAGE_B)   // 65536

__device__ __forceinline__ uint32_t swA(uint32_t off) { return off ^ ((off >> 3) & 0x30); }
__device__ __forceinline__ uint32_t swB(uint32_t off) { return off ^ ((off >> 4) & 0x70); }

__global__ __launch_bounds__(256, 2)
void mma_gemm_kernel(const float* __restrict__ bias, float* __restrict__ C) {
    extern __shared__ char smem[];
    const uint32_t sb = smem_u32(smem);
    const int tid  = threadIdx.x;
    const int lane = tid & 31;
    const int wid  = tid >> 5;
    const int bm = blockIdx.y * BM;
    const int bn = blockIdx.x * BN;
    const int wm = (wid >> 2) * 64;   // 0 / 64
    const int wn = (wid & 3) * 32;    // 0..96

    float acc[4][4][4];
#pragma unroll
    for (int i = 0; i < 4; ++i)
#pragma unroll
        for (int j = 0; j < 4; ++j)
#pragma unroll
            for (int q = 0; q < 4; ++q) acc[i][j][q] = 0.0f;

    auto load_stage = [&](int slot, int kt) {
        const uint32_t st = sb + slot * STAGE_B;
        const size_t ka = (size_t)kt * BK;
        // A: 128 rows x 4 x 16B units = 512 -> 2 per thread
#pragma unroll
        for (int it = 0; it < 2; ++it) {
            int p = tid + it * 256;
            int m = p >> 2, u = p & 3;
            uint32_t sw = swA((uint32_t)m * 64 + u * 16);
            cp16(st + OFF_A + sw, g_a + (size_t)(bm + m) * HH + ka + u * 8);
        }
        // B: 32 rows x 16 x 16B units = 512 -> 2 per thread
#pragma unroll
        for (int it = 0; it < 2; ++it) {
            int p = tid + it * 256;
            int k = p >> 4, u = p & 15;
            uint32_t sw = swB((uint32_t)k * 256 + u * 16);
            cp16(st + OFF_B + sw, g_w + (size_t)(ka + k) * VV + bn + u * 8);
        }
        asm volatile("cp.async.commit_group;");
    };

#pragma unroll
    for (int s = 0; s < STAGES - 1; ++s) load_stage(s, s);

    for (int kt = 0; kt < KTILES; ++kt) {
        asm volatile("cp.async.wait_group 2;");
        __syncthreads();
        const uint32_t st = sb + (kt & (STAGES - 1)) * STAGE_B;

#pragma unroll
        for (int h = 0; h < 2; ++h) {
            const int k16 = h * 16;
            uint32_t af[4][4];
#pragma unroll
            for (int i = 0; i < 4; ++i) {
                uint32_t row = wm + i * 16 + (lane & 15);
                uint32_t u = (uint32_t)(k16 >> 3) + (lane >> 4);
                ldsm4(af[i], st + OFF_A + swA(row * 64 + u * 16));
            }
            // B: warp covers 32 cols = 2 ldsm4t (16 cols each)
            uint32_t bf[2][4];
#pragma unroll
            for (int j2 = 0; j2 < 2; ++j2) {
                uint32_t bk = (uint32_t)k16 + (lane & 15);
                uint32_t u = (uint32_t)((wn + 16 * j2) >> 3) + (lane >> 4);
                ldsm4t(bf[j2], st + OFF_B + swB(bk * 256 + u * 16));
            }
#pragma unroll
            for (int i = 0; i < 4; ++i) {
                mma_f16(acc[i][0], af[i], bf[0]);
                mma_f16(acc[i][1], af[i], bf[0] + 2);
                mma_f16(acc[i][2], af[i], bf[1]);
                mma_f16(acc[i][3], af[i], bf[1] + 2);
            }
        }
        if (kt + STAGES - 1 < KTILES) load_stage((kt + STAGES - 1) & (STAGES - 1), kt + STAGES - 1);
        else asm volatile("cp.async.commit_group;");
    }

    // ---- epilogue: bias + store ----
    const int rbase = bm + wm + (lane >> 2);
    const int cbase = bn + wn + (lane & 3) * 2;
#pragma unroll
    for (int j = 0; j < 4; ++j) {
        const int c = cbase + j * 8;
        const float bx = __ldg(&bias[c]);
        const float by = __ldg(&bias[c + 1]);
#pragma unroll
        for (int i = 0; i < 4; ++i) {
            const int r = rbase + i * 16;
            float2 v0 = make_float2(acc[i][j][0] + bx, acc[i][j][1] + by);
            float2 v1 = make_float2(acc[i][j][2] + bx, acc[i][j][3] + by);
            *reinterpret_cast<float2*>(&C[(size_t)r * VV + c]) = v0;
            *reinterpret_cast<float2*>(&C[(size_t)(r + 8) * VV + c]) = v1;
        }
    }
}

// ---------------------------------------------------------------------------
// Launch
// ---------------------------------------------------------------------------
extern "C" void kernel_launch(void* const* d_in, const int* in_sizes, int n_in,
                              void* d_out, int out_size) {
    const float* enc  = (const float*)d_in[0];   // [32,512,768]
    const int*   ids  = (const int*)  d_in[1];   // [32,512]
    const float* W    = (const float*)d_in[2];   // [768,8192]
    const float* bias = (const float*)d_in[3];   // [8192]
    float* out = (float*)d_out;                  // [32,256,8192]

    segmean_kernel<<<dim3(WMAX / WPB, BB), 192>>>(enc, ids);

    const size_t total4 = (size_t)HH * VV / 4;
    wconv_kernel<<<(unsigned)((total4 + 255) / 256), 256>>>(W);

    cudaFuncSetAttribute(mma_gemm_kernel,
                         cudaFuncAttributeMaxDynamicSharedMemorySize, SMEM_TOTAL);
    mma_gemm_kernel<<<dim3(VV / BN, MM / BM), 256, SMEM_TOTAL>>>(bias, out);
}

// round 6
// speedup vs baseline: 7.5792x; 1.0385x over previous
#include <cuda_runtime.h>
#include <cuda_fp16.h>
#include <cstdint>

#define BB   32
#define SS   512
#define HH   768
#define VV   8192
#define WMAX 256
#define MM   (BB * WMAX)       // 8192

// ---------------------------------------------------------------------------
// Device scratch: A (merged) fp16 [M, K] row-major; W fp16 [K, N].
// ---------------------------------------------------------------------------
__device__ __align__(16) __half g_a[(size_t)MM * HH];
__device__ __align__(16) __half g_w[(size_t)HH * VV];

// ---------------------------------------------------------------------------
// PTX helpers — family-portable (sm_80+)
// ---------------------------------------------------------------------------
__device__ __forceinline__ uint32_t smem_u32(const void* p) {
    uint32_t a;
    asm("{ .reg .u64 t; cvta.to.shared.u64 t, %1; cvt.u32.u64 %0, t; }" : "=r"(a) : "l"(p));
    return a;
}
__device__ __forceinline__ void cp16(uint32_t s, const void* g) {
    asm volatile("cp.async.cg.shared.global [%0], [%1], 16;" :: "r"(s), "l"(g));
}
__device__ __forceinline__ void ldsm4(uint32_t* r, uint32_t addr) {
    asm volatile("ldmatrix.sync.aligned.m8n8.x4.shared.b16 {%0,%1,%2,%3}, [%4];"
                 : "=r"(r[0]), "=r"(r[1]), "=r"(r[2]), "=r"(r[3]) : "r"(addr));
}
__device__ __forceinline__ void ldsm4t(uint32_t* r, uint32_t addr) {
    asm volatile("ldmatrix.sync.aligned.m8n8.x4.trans.shared.b16 {%0,%1,%2,%3}, [%4];"
                 : "=r"(r[0]), "=r"(r[1]), "=r"(r[2]), "=r"(r[3]) : "r"(addr));
}
__device__ __forceinline__ void mma_f16(float* d, const uint32_t* a, const uint32_t* b) {
    asm volatile(
        "mma.sync.aligned.m16n8k16.row.col.f32.f16.f16.f32 "
        "{%0,%1,%2,%3}, {%4,%5,%6,%7}, {%8,%9}, {%0,%1,%2,%3};"
        : "+f"(d[0]), "+f"(d[1]), "+f"(d[2]), "+f"(d[3])
        : "r"(a[0]), "r"(a[1]), "r"(a[2]), "r"(a[3]), "r"(b[0]), "r"(b[1]));
}

// ---------------------------------------------------------------------------
// Fused prep kernel. Blocks [0, SEG_BLOCKS): segment-mean (run-streaming).
// Blocks [SEG_BLOCKS, ...): W fp32 -> fp16 conversion. 192 threads each.
// ---------------------------------------------------------------------------
#define WPB        8
#define SEG_BLOCKS ((WMAX / WPB) * BB)                 // 1024
#define WC_TOTAL4  ((size_t)HH * VV / 4)               // 1572864
#define WC_BLOCKS  ((unsigned)((WC_TOTAL4 + 191) / 192))  // 8192

__global__ __launch_bounds__(192)
void prep_kernel(const float* __restrict__ enc,
                 const int*   __restrict__ ids,
                 const float* __restrict__ W) {
    const int tid = threadIdx.x;

    if (blockIdx.x >= SEG_BLOCKS) {
        // ---- W convert ----
        size_t idx = (size_t)(blockIdx.x - SEG_BLOCKS) * 192 + tid;
        if (idx < WC_TOTAL4) {
            float4 v = reinterpret_cast<const float4*>(W)[idx];
            __half2* p = reinterpret_cast<__half2*>(g_w) + idx * 2;
            p[0] = __halves2half2(__float2half_rn(v.x), __float2half_rn(v.y));
            p[1] = __halves2half2(__float2half_rn(v.z), __float2half_rn(v.w));
        }
        return;
    }

    // ---- segment mean for WPB consecutive words ----
    __shared__ int srow[SS];
    const int b  = blockIdx.x / (WMAX / WPB);
    const int w0 = (blockIdx.x % (WMAX / WPB)) * WPB;

    for (int i = tid; i < SS; i += 192) srow[i] = ids[b * SS + i];
    __syncthreads();

    // token range covering words [w0, w0+WPB)
    int lo = 0, r = SS;
    while (lo < r) { int m = (lo + r) >> 1; if (srow[m] < w0) lo = m + 1; else r = m; }
    int hi = lo; r = SS;
    while (hi < r) { int m = (hi + r) >> 1; if (srow[m] < w0 + WPB) hi = m + 1; else r = m; }

    const float* base = enc + (size_t)b * SS * HH + tid * 4;
    const size_t obase = (size_t)(b * WMAX) * HH + tid * 4;

    unsigned present = 0;
    int t = lo;
    while (t < hi) {
        const int w = srow[t];
        int e = t + 1;
        while (e < hi && srow[e] == w) ++e;   // run end (uniform smem scan)

        float4 s0 = make_float4(0.f, 0.f, 0.f, 0.f);
        float4 s1 = make_float4(0.f, 0.f, 0.f, 0.f);
        int u = t;
        for (; u + 1 < e; u += 2) {
            float4 v0 = *reinterpret_cast<const float4*>(base + (size_t)u * HH);
            float4 v1 = *reinterpret_cast<const float4*>(base + (size_t)(u + 1) * HH);
            s0.x += v0.x; s0.y += v0.y; s0.z += v0.z; s0.w += v0.w;
            s1.x += v1.x; s1.y += v1.y; s1.z += v1.z; s1.w += v1.w;
        }
        if (u < e) {
            float4 v0 = *reinterpret_cast<const float4*>(base + (size_t)u * HH);
            s0.x += v0.x; s0.y += v0.y; s0.z += v0.z; s0.w += v0.w;
        }
        const float inv = 1.0f / (float)(e - t);
        __half2* p = reinterpret_cast<__half2*>(g_a + obase + (size_t)w * HH);
        p[0] = __halves2half2(__float2half_rn((s0.x + s1.x) * inv),
                              __float2half_rn((s0.y + s1.y) * inv));
        p[1] = __halves2half2(__float2half_rn((s0.z + s1.z) * inv),
                              __float2half_rn((s0.w + s1.w) * inv));
        present |= 1u << (w - w0);
        t = e;
    }
    // zero-fill absent words
#pragma unroll
    for (int wl = 0; wl < WPB; ++wl) {
        if (!(present & (1u << wl))) {
            __half2 z = __halves2half2(__float2half_rn(0.f), __float2half_rn(0.f));
            __half2* p = reinterpret_cast<__half2*>(g_a + obase + (size_t)(w0 + wl) * HH);
            p[0] = z; p[1] = z;
        }
    }
}

// ---------------------------------------------------------------------------
// HMMA GEMM.  C = A * W + bias, fp16 x fp16 -> fp32.
// CTA 128x128, BK=64, 3-stage cp.async, 8 warps (2x4), warp tile 64x32.
// 2 CTAs / SM (96 KB smem each, <=128 regs).
// ---------------------------------------------------------------------------
#define BM 128
#define BN 128
#define BK 64
#define KTILES   (HH / BK)     // 12
#define STAGES   3
#define OFF_A    0             // [128][64] fp16 = 16 KB (128B rows)
#define OFF_B    16384         // [64][128] fp16 = 16 KB (256B rows)
#define STAGE_B  32768
#define SMEM_TOTAL (STAGES * STAGE_B)   // 98304

__device__ __forceinline__ uint32_t swA(uint32_t off) { return off ^ ((off >> 3) & 0x70); }
__device__ __forceinline__ uint32_t swB(uint32_t off) { return off ^ ((off >> 4) & 0x70); }

__global__ __launch_bounds__(256, 2)
void mma_gemm_kernel(const float* __restrict__ bias, float* __restrict__ C) {
    extern __shared__ char smem[];
    const uint32_t sb = smem_u32(smem);
    const int tid  = threadIdx.x;
    const int lane = tid & 31;
    const int wid  = tid >> 5;
    const int bm = blockIdx.y * BM;
    const int bn = blockIdx.x * BN;
    const int wm = (wid >> 2) * 64;   // 0 / 64
    const int wn = (wid & 3) * 32;    // 0..96

    float acc[4][4][4];
#pragma unroll
    for (int i = 0; i < 4; ++i)
#pragma unroll
        for (int j = 0; j < 4; ++j)
#pragma unroll
            for (int q = 0; q < 4; ++q) acc[i][j][q] = 0.0f;

    auto load_stage = [&](int slot, int kt) {
        const uint32_t st = sb + slot * STAGE_B;
        const size_t ka = (size_t)kt * BK;
        // A: 128 rows x 8 x 16B units = 1024 -> 4 per thread
#pragma unroll
        for (int it = 0; it < 4; ++it) {
            int p = tid + it * 256;
            int m = p >> 3, u = p & 7;
            cp16(st + OFF_A + swA((uint32_t)m * 128 + u * 16),
                 g_a + (size_t)(bm + m) * HH + ka + u * 8);
        }
        // B: 64 rows x 16 x 16B units = 1024 -> 4 per thread
#pragma unroll
        for (int it = 0; it < 4; ++it) {
            int p = tid + it * 256;
            int k = p >> 4, u = p & 15;
            cp16(st + OFF_B + swB((uint32_t)k * 256 + u * 16),
                 g_w + (size_t)(ka + k) * VV + bn + u * 8);
        }
        asm volatile("cp.async.commit_group;");
    };

#pragma unroll
    for (int s = 0; s < STAGES - 1; ++s) load_stage(s, s);

    for (int kt = 0; kt < KTILES; ++kt) {
        asm volatile("cp.async.wait_group 1;");
        __syncthreads();
        const uint32_t st = sb + (kt % STAGES) * STAGE_B;

#pragma unroll
        for (int h = 0; h < 4; ++h) {            // 4 x k16 per BK=64
            const int k16 = h * 16;
            uint32_t af[4][4];
#pragma unroll
            for (int i = 0; i < 4; ++i) {
                uint32_t row = wm + i * 16 + (lane & 15);
                uint32_t u = (uint32_t)(k16 >> 3) + (lane >> 4);
                ldsm4(af[i], st + OFF_A + swA(row * 128 + u * 16));
            }
            uint32_t bf[2][4];
#pragma unroll
            for (int j2 = 0; j2 < 2; ++j2) {
                uint32_t bk = (uint32_t)k16 + (lane & 15);
                uint32_t u = (uint32_t)((wn + 16 * j2) >> 3) + (lane >> 4);
                ldsm4t(bf[j2], st + OFF_B + swB(bk * 256 + u * 16));
            }
#pragma unroll
            for (int i = 0; i < 4; ++i) {
                mma_f16(acc[i][0], af[i], bf[0]);
                mma_f16(acc[i][1], af[i], bf[0] + 2);
                mma_f16(acc[i][2], af[i], bf[1]);
                mma_f16(acc[i][3], af[i], bf[1] + 2);
            }
        }
        if (kt + STAGES - 1 < KTILES)
            load_stage((kt + STAGES - 1) % STAGES, kt + STAGES - 1);
        else
            asm volatile("cp.async.commit_group;");
    }

    // ---- epilogue: bias + store ----
    const int rbase = bm + wm + (lane >> 2);
    const int cbase = bn + wn + (lane & 3) * 2;
#pragma unroll
    for (int j = 0; j < 4; ++j) {
        const int c = cbase + j * 8;
        const float bx = __ldg(&bias[c]);
        const float by = __ldg(&bias[c + 1]);
#pragma unroll
        for (int i = 0; i < 4; ++i) {
            const int r = rbase + i * 16;
            float2 v0 = make_float2(acc[i][j][0] + bx, acc[i][j][1] + by);
            float2 v1 = make_float2(acc[i][j][2] + bx, acc[i][j][3] + by);
            *reinterpret_cast<float2*>(&C[(size_t)r * VV + c]) = v0;
            *reinterpret_cast<float2*>(&C[(size_t)(r + 8) * VV + c]) = v1;
        }
    }
}

// ---------------------------------------------------------------------------
// Launch
// ---------------------------------------------------------------------------
extern "C" void kernel_launch(void* const* d_in, const int* in_sizes, int n_in,
                              void* d_out, int out_size) {
    const float* enc  = (const float*)d_in[0];   // [32,512,768]
    const int*   ids  = (const int*)  d_in[1];   // [32,512]
    const float* W    = (const float*)d_in[2];   // [768,8192]
    const float* bias = (const float*)d_in[3];   // [8192]
    float* out = (float*)d_out;                  // [32,256,8192]

    prep_kernel<<<SEG_BLOCKS + WC_BLOCKS, 192>>>(enc, ids, W);

    cudaFuncSetAttribute(mma_gemm_kernel,
                         cudaFuncAttributeMaxDynamicSharedMemorySize, SMEM_TOTAL);
    mma_gemm_kernel<<<dim3(VV / BN, MM / BM), 256, SMEM_TOTAL>>>(bias, out);
}